// round 12
// baseline (speedup 1.0000x reference)
#include <cuda_runtime.h>
#include <cuda_fp16.h>
#include <cstdint>

#define BATCH 32
#define HH 512
#define WW 512
#define NPX (BATCH * HH * WW)

#define TX 64   // output tile width
#define TY 32   // output tile height
#define SW 72   // smem tile width  (TX + 8)
#define SH2 40  // smem tile height (TY + 8)

typedef unsigned long long u64;

// Pre-duplicated 9x9 weight pairs {w,w} in constant bank: one LDC.64 per
// weight, no broadcast MOVs, half the constant-port transactions.
__constant__ u64 c_w2[81];

// Scratch (device globals: allocation-free per harness rules)
__device__ __half g_lm[NPX];   // local mean, fp16
__device__ __half g_s2[NPX];   // channel-mean squared-dev, fp16
__device__ __half g_sig[NPX];  // sigma, fp16
__device__ float  g_part[BATCH * 128];

// --- f32x2 packed-math helpers (Blackwell FFMA2 path) ----------------------
__device__ __forceinline__ void fma2(u64& acc, u64 a, u64 b) {
    asm("fma.rn.f32x2 %0, %1, %2, %0;" : "+l"(acc) : "l"(a), "l"(b));
}
// {lo = hi32(a), hi = lo32(b)} : odd-tap pair from two aligned pairs (MOVs)
__device__ __forceinline__ u64 pair_merge(u64 a, u64 b) {
    u64 r;
    asm("mov.b64 %0, {%1, %2};"
        : "=l"(r) : "r"((uint32_t)(a >> 32)), "r"((uint32_t)b));
    return r;
}

// ---------------------------------------------------------------------------
// Blur core (double-pair register scheme): thread = 2 adjacent cols x 4 out
// rows (12-row window). 60 conflict-free LDS.64/thread; odd taps via register
// merge; weight pairs via single LDC.64 each from c_w2.
// ---------------------------------------------------------------------------
__device__ __forceinline__ void blur4(const float* sm, int tx, int tz,
                                      u64 acc[4]) {
#pragma unroll
    for (int i = 0; i < 4; i++) acc[i] = 0ull;

    const u64* b64 = (const u64*)sm + 2 * tz * SW + tx;

    u64 cur0[12], cur1[12];
#pragma unroll
    for (int j = 0; j < 12; j++) cur0[j] = b64[j * (SW / 2)];

#pragma unroll
    for (int p = 0; p < 4; p++) {
#pragma unroll
        for (int ky = 0; ky < 9; ky++) {
            u64 we = c_w2[ky * 9 + 2 * p];
#pragma unroll
            for (int oy = 0; oy < 4; oy++) fma2(acc[oy], we, cur0[ky + oy]);
        }
#pragma unroll
        for (int j = 0; j < 12; j++) cur1[j] = b64[j * (SW / 2) + p + 1];
#pragma unroll
        for (int j = 0; j < 12; j++) cur0[j] = pair_merge(cur0[j], cur1[j]);
#pragma unroll
        for (int ky = 0; ky < 9; ky++) {
            u64 wo = c_w2[ky * 9 + 2 * p + 1];
#pragma unroll
            for (int oy = 0; oy < 4; oy++) fma2(acc[oy], wo, cur0[ky + oy]);
        }
#pragma unroll
        for (int j = 0; j < 12; j++) cur0[j] = cur1[j];
    }
#pragma unroll
    for (int ky = 0; ky < 9; ky++) {
        u64 we = c_w2[ky * 9 + 8];
#pragma unroll
        for (int oy = 0; oy < 4; oy++) fma2(acc[oy], we, cur0[ky + oy]);
    }
}

// ---------------------------------------------------------------------------
// Stage 1: vectorized fill (4 px/group: 3x LDG.128 -> m f32 + q fp16 tiles),
// blur m -> lm, s2 = q - 2*lm*m + lm^2. smem = 17.3 KB dynamic.
// ---------------------------------------------------------------------------
__global__ __launch_bounds__(256, 4) void k_stage1(const float* __restrict__ x) {
    extern __shared__ float dsm[];
    float*  sm = dsm;                         // [SH2][SW] f32
    __half* sq = (__half*)(dsm + SH2 * SW);   // [SH2][SW] fp16

    const int b = blockIdx.z;
    const int x0 = blockIdx.x * TX, y0 = blockIdx.y * TY;
    const int tid = threadIdx.y * 32 + threadIdx.x;
    const float inv3 = 1.f / 3.f;

    {
        int r = tid / 18, c = tid - r * 18;
        for (int g = tid; g < SH2 * (SW / 4); g += 256) {
            int gy = y0 - 4 + r, gx = x0 - 4 + 4 * c;
            float m0 = 0, m1 = 0, m2 = 0, m3 = 0;
            float q0 = 0, q1 = 0, q2 = 0, q3 = 0;
            if ((unsigned)gy < (unsigned)HH && (unsigned)gx < (unsigned)WW) {
                const float4* p =
                    (const float4*)(x + ((size_t)(b * HH + gy) * WW + gx) * 3);
                float4 A = __ldcs(p), B = __ldcs(p + 1), C = __ldcs(p + 2);
                m0 = (A.x + A.y + A.z) * inv3;
                m1 = (A.w + B.x + B.y) * inv3;
                m2 = (B.z + B.w + C.x) * inv3;
                m3 = (C.y + C.z + C.w) * inv3;
                q0 = fmaf(A.x, A.x, fmaf(A.y, A.y, A.z * A.z)) * inv3;
                q1 = fmaf(A.w, A.w, fmaf(B.x, B.x, B.y * B.y)) * inv3;
                q2 = fmaf(B.z, B.z, fmaf(B.w, B.w, C.x * C.x)) * inv3;
                q3 = fmaf(C.y, C.y, fmaf(C.z, C.z, C.w * C.w)) * inv3;
            }
            int i = r * SW + 4 * c;
            *(float4*)&sm[i] = make_float4(m0, m1, m2, m3);
            __half2 qa = __floats2half2_rn(q0, q1);
            __half2 qb = __floats2half2_rn(q2, q3);
            *(uint2*)&sq[i] = make_uint2(*(uint32_t*)&qa, *(uint32_t*)&qb);
            c += 4; r += 14;                  // 256 = 14*18 + 4
            if (c >= 18) { c -= 18; r += 1; }
        }
    }
    __syncthreads();

    const int tx = threadIdx.x, tz = threadIdx.y;
    u64 acc[4];
    blur4(sm, tx, tz, acc);

#pragma unroll
    for (int oy = 0; oy < 4; oy++) {
        float lm0 = __uint_as_float((uint32_t)acc[oy]);
        float lm1 = __uint_as_float((uint32_t)(acc[oy] >> 32));
        int si = (4 * tz + oy + 4) * SW + 2 * tx + 4;
        float2 mm = *(const float2*)&sm[si];
        float2 qq = __half22float2(*(const __half2*)&sq[si]);
        float s20 = fmaxf(fmaf(lm0, fmaf(-2.f, mm.x, lm0), qq.x), 0.f);
        float s21 = fmaxf(fmaf(lm1, fmaf(-2.f, mm.y, lm1), qq.y), 0.f);
        int idx = (b * HH + y0 + 4 * tz + oy) * WW + x0 + 2 * tx;
        __stcs((__half2*)&g_lm[idx], __floats2half2_rn(lm0, lm1));
        __stcs((__half2*)&g_s2[idx], __floats2half2_rn(s20, s21));
    }
}

// ---------------------------------------------------------------------------
// Stage 2: fill ss (f32) from fp16 s2, blur -> sigma = sqrt(.), write sigma
// fp16 + per-block partials. smem = 11.5 KB static.
// ---------------------------------------------------------------------------
__global__ __launch_bounds__(256, 4) void k_stage2() {
    __shared__ __align__(16) float ss[SH2 * SW];
    __shared__ float warpsum[8];

    const int b = blockIdx.z;
    const int x0 = blockIdx.x * TX, y0 = blockIdx.y * TY;
    const int tid = threadIdx.y * 32 + threadIdx.x;

    {
        int r = tid / 18, c = tid - r * 18;
        for (int g = tid; g < SH2 * (SW / 4); g += 256) {
            int gy = y0 - 4 + r, gx = x0 - 4 + 4 * c;
            float f0 = 0, f1 = 0, f2 = 0, f3 = 0;
            if ((unsigned)gy < (unsigned)HH && (unsigned)gx < (unsigned)WW) {
                uint2 u = __ldcs((const uint2*)&g_s2[(b * HH + gy) * WW + gx]);
                float2 a = __half22float2(*(__half2*)&u.x);
                float2 d = __half22float2(*(__half2*)&u.y);
                f0 = a.x; f1 = a.y; f2 = d.x; f3 = d.y;
            }
            int i = r * SW + 4 * c;
            *(float4*)&ss[i] = make_float4(f0, f1, f2, f3);
            c += 4; r += 14;
            if (c >= 18) { c -= 18; r += 1; }
        }
    }
    __syncthreads();

    const int tx = threadIdx.x, tz = threadIdx.y;
    u64 acc[4];
    blur4(ss, tx, tz, acc);

    float lsum = 0.f;
#pragma unroll
    for (int oy = 0; oy < 4; oy++) {
        float s0 = sqrtf(fmaxf(__uint_as_float((uint32_t)acc[oy]), 0.f));
        float s1 = sqrtf(fmaxf(__uint_as_float((uint32_t)(acc[oy] >> 32)), 0.f));
        int idx = (b * HH + y0 + 4 * tz + oy) * WW + x0 + 2 * tx;
        __stcs((__half2*)&g_sig[idx], __floats2half2_rn(s0, s1));
        lsum += s0 + s1;
    }

#pragma unroll
    for (int o = 16; o > 0; o >>= 1)
        lsum += __shfl_down_sync(0xFFFFFFFFu, lsum, o);
    if (tx == 0) warpsum[tz] = lsum;
    __syncthreads();
    if (tid == 0) {
        float t = 0.f;
#pragma unroll
        for (int i = 0; i < 8; i++) t += warpsum[i];
        g_part[b * 128 + blockIdx.y * 8 + blockIdx.x] = t;
    }
}

// ---------------------------------------------------------------------------
// Final: prologue re-reduces this batch's 128 partials (L2 hits) -> ms, then
// out = (x - lm) / max(ms, sigma). 8 px / thread, streaming float4 traffic.
// ---------------------------------------------------------------------------
__global__ __launch_bounds__(256) void k_final(const float* __restrict__ x,
                                               float* __restrict__ out) {
    __shared__ float s_w[4];
    __shared__ float s_ms;

    const int b = blockIdx.x >> 7;  // 128 blocks / batch
    if (threadIdx.x < 128) {
        float v = g_part[b * 128 + threadIdx.x];
#pragma unroll
        for (int o = 16; o > 0; o >>= 1)
            v += __shfl_down_sync(0xFFFFFFFFu, v, o);
        if ((threadIdx.x & 31) == 0) s_w[threadIdx.x >> 5] = v;
    }
    __syncthreads();
    if (threadIdx.x == 0)
        s_ms = (s_w[0] + s_w[1] + s_w[2] + s_w[3]) *
               (1.f / ((float)HH * (float)WW));
    __syncthreads();
    const float ms = s_ms;

    const int p = (blockIdx.x & 127) * 2048 + threadIdx.x * 8 + (b << 18);

    uint4 lmu = __ldcs((const uint4*)((const __half*)g_lm + p));
    uint4 sgu = __ldcs((const uint4*)((const __half*)g_sig + p));
    const __half2* lmh = (const __half2*)&lmu;
    const __half2* sgh = (const __half2*)&sgu;

    const float4* xp = (const float4*)(x + (size_t)p * 3);
    float4 xv[6];
#pragma unroll
    for (int i = 0; i < 6; i++) xv[i] = __ldcs(xp + i);

    float lmv[8], inv[8];
#pragma unroll
    for (int i = 0; i < 4; i++) {
        float2 l = __half22float2(lmh[i]);
        float2 s = __half22float2(sgh[i]);
        lmv[2 * i] = l.x;
        lmv[2 * i + 1] = l.y;
        inv[2 * i] = __frcp_rn(fmaxf(ms, s.x));
        inv[2 * i + 1] = __frcp_rn(fmaxf(ms, s.y));
    }

    const float* f = (const float*)xv;
    float4* op = (float4*)(out + (size_t)p * 3);
#pragma unroll
    for (int i = 0; i < 6; i++) {
        float o0 = (f[4 * i + 0] - lmv[(4 * i + 0) / 3]) * inv[(4 * i + 0) / 3];
        float o1 = (f[4 * i + 1] - lmv[(4 * i + 1) / 3]) * inv[(4 * i + 1) / 3];
        float o2 = (f[4 * i + 2] - lmv[(4 * i + 2) / 3]) * inv[(4 * i + 2) / 3];
        float o3 = (f[4 * i + 3] - lmv[(4 * i + 3) / 3]) * inv[(4 * i + 3) / 3];
        __stcs(op + i, make_float4(o0, o1, o2, o3));
    }
}

// ---------------------------------------------------------------------------
extern "C" void kernel_launch(void* const* d_in, const int* in_sizes, int n_in,
                              void* d_out, int out_size) {
    const float* x = (const float*)d_in[0];

    // Build duplicated weight pairs {w,w} directly into c_w2 with two strided
    // D2D 2D-copies (graph-capturable memcpy nodes; no kernel, no alloc).
    void* w2addr = nullptr;
    cudaGetSymbolAddress(&w2addr, c_w2);
    cudaMemcpy2DAsync(w2addr, 8, d_in[1], 4, 4, 81,
                      cudaMemcpyDeviceToDevice, 0);               // low words
    cudaMemcpy2DAsync((char*)w2addr + 4, 8, d_in[1], 4, 4, 81,
                      cudaMemcpyDeviceToDevice, 0);               // high words

    const int smem1 = SH2 * SW * (int)sizeof(float) +
                      SH2 * SW * (int)sizeof(__half);  // 17280 B
    cudaFuncSetAttribute(k_stage1, cudaFuncAttributeMaxDynamicSharedMemorySize,
                         smem1);

    dim3 blk(32, 8);
    dim3 grd(WW / TX, HH / TY, BATCH);  // (8, 16, 32) = 4096 blocks
    k_stage1<<<grd, blk, smem1>>>(x);
    k_stage2<<<grd, blk>>>();
    k_final<<<BATCH * 128, 256>>>(x, (float*)d_out);
}

// round 13
// speedup vs baseline: 1.5457x; 1.5457x over previous
#include <cuda_runtime.h>
#include <cuda_fp16.h>
#include <cstdint>

#define BATCH 32
#define HH 512
#define WW 512
#define NPX (BATCH * HH * WW)

#define TX 64   // output tile width
#define TY 32   // output tile height
#define SW 72   // smem tile width  (TX + 8)
#define SH2 40  // smem tile height (TY + 8)

typedef unsigned long long u64;

// 9x9 kernel weights in constant bank (R9 scheme: LDC.32 + broadcast MOV)
__constant__ float c_w[81];

// Scratch (device globals: allocation-free per harness rules)
__device__ __half g_v[NPX * 3]; // v = x - lm, fp16, 3 channels
__device__ __half g_s2[NPX];    // channel-mean squared-dev, fp16
__device__ __half g_sig[NPX];   // sigma, fp16
__device__ float  g_part[BATCH * 128];

// --- f32x2 packed-math helpers (Blackwell FFMA2 path) ----------------------
__device__ __forceinline__ u64 bcast2(float w) {
    u64 r;
    asm("mov.b64 %0, {%1, %1};" : "=l"(r) : "r"(__float_as_uint(w)));
    return r;
}
__device__ __forceinline__ void fma2(u64& acc, u64 a, u64 b) {
    asm("fma.rn.f32x2 %0, %1, %2, %0;" : "+l"(acc) : "l"(a), "l"(b));
}
// {lo = hi32(a), hi = lo32(b)} : odd-tap pair from two aligned pairs (MOVs)
__device__ __forceinline__ u64 pair_merge(u64 a, u64 b) {
    u64 r;
    asm("mov.b64 %0, {%1, %2};"
        : "=l"(r) : "r"((uint32_t)(a >> 32)), "r"((uint32_t)b));
    return r;
}

// ---------------------------------------------------------------------------
// Blur core (double-pair register scheme, R9-proven): thread = 2 adjacent
// cols x 4 out rows (12-row window). 60 conflict-free LDS.64/thread; odd taps
// via register merge; weights via LDC.32 + broadcast MOV.
// ---------------------------------------------------------------------------
__device__ __forceinline__ void blur4(const float* sm, int tx, int tz,
                                      u64 acc[4]) {
#pragma unroll
    for (int i = 0; i < 4; i++) acc[i] = 0ull;

    const u64* b64 = (const u64*)sm + 2 * tz * SW + tx;

    u64 cur0[12], cur1[12];
#pragma unroll
    for (int j = 0; j < 12; j++) cur0[j] = b64[j * (SW / 2)];

#pragma unroll
    for (int p = 0; p < 4; p++) {
#pragma unroll
        for (int ky = 0; ky < 9; ky++) {
            u64 we = bcast2(c_w[ky * 9 + 2 * p]);
#pragma unroll
            for (int oy = 0; oy < 4; oy++) fma2(acc[oy], we, cur0[ky + oy]);
        }
#pragma unroll
        for (int j = 0; j < 12; j++) cur1[j] = b64[j * (SW / 2) + p + 1];
#pragma unroll
        for (int j = 0; j < 12; j++) cur0[j] = pair_merge(cur0[j], cur1[j]);
#pragma unroll
        for (int ky = 0; ky < 9; ky++) {
            u64 wo = bcast2(c_w[ky * 9 + 2 * p + 1]);
#pragma unroll
            for (int oy = 0; oy < 4; oy++) fma2(acc[oy], wo, cur0[ky + oy]);
        }
#pragma unroll
        for (int j = 0; j < 12; j++) cur0[j] = cur1[j];
    }
#pragma unroll
    for (int ky = 0; ky < 9; ky++) {
        u64 we = bcast2(c_w[ky * 9 + 8]);
#pragma unroll
        for (int oy = 0; oy < 4; oy++) fma2(acc[oy], we, cur0[ky + oy]);
    }
}

// ---------------------------------------------------------------------------
// Stage 1: fill m (f32) + q (fp16) tiles AND keep interior x as fp16 (3ch) in
// smem; blur m -> lm; write v = x - lm (fp16 x3) and s2. lm never hits DRAM.
// smem = 17280 (m,q) + 12288 (x interior) = 29568 B dynamic -> 4 CTA/SM.
// ---------------------------------------------------------------------------
__global__ __launch_bounds__(256, 4) void k_stage1(const float* __restrict__ x) {
    extern __shared__ float dsm[];
    float*  sm = dsm;                              // [SH2][SW] f32 m
    __half* sq = (__half*)(dsm + SH2 * SW);        // [SH2][SW] fp16 q
    __half* xt = sq + SH2 * SW;                    // [32][64*3] fp16 x interior

    const int b = blockIdx.z;
    const int x0 = blockIdx.x * TX, y0 = blockIdx.y * TY;
    const int tid = threadIdx.y * 32 + threadIdx.x;
    const float inv3 = 1.f / 3.f;

    {
        int r = tid / 18, c = tid - r * 18;
        for (int g = tid; g < SH2 * (SW / 4); g += 256) {
            int gy = y0 - 4 + r, gx = x0 - 4 + 4 * c;
            float m0 = 0, m1 = 0, m2 = 0, m3 = 0;
            float q0 = 0, q1 = 0, q2 = 0, q3 = 0;
            if ((unsigned)gy < (unsigned)HH && (unsigned)gx < (unsigned)WW) {
                const float4* p =
                    (const float4*)(x + ((size_t)(b * HH + gy) * WW + gx) * 3);
                float4 A = __ldcs(p), B = __ldcs(p + 1), C = __ldcs(p + 2);
                m0 = (A.x + A.y + A.z) * inv3;
                m1 = (A.w + B.x + B.y) * inv3;
                m2 = (B.z + B.w + C.x) * inv3;
                m3 = (C.y + C.z + C.w) * inv3;
                q0 = fmaf(A.x, A.x, fmaf(A.y, A.y, A.z * A.z)) * inv3;
                q1 = fmaf(A.w, A.w, fmaf(B.x, B.x, B.y * B.y)) * inv3;
                q2 = fmaf(B.z, B.z, fmaf(B.w, B.w, C.x * C.x)) * inv3;
                q3 = fmaf(C.y, C.y, fmaf(C.z, C.z, C.w * C.w)) * inv3;
                if (r >= 4 && r < 36 && c >= 1 && c < 17) {
                    // interior 4-px group -> 12 halves = 6 uint32
                    uint32_t* dst = (uint32_t*)xt + (r - 4) * 96 + 6 * (c - 1);
                    __half2 h0 = __floats2half2_rn(A.x, A.y);
                    __half2 h1 = __floats2half2_rn(A.z, A.w);
                    __half2 h2 = __floats2half2_rn(B.x, B.y);
                    __half2 h3 = __floats2half2_rn(B.z, B.w);
                    __half2 h4 = __floats2half2_rn(C.x, C.y);
                    __half2 h5 = __floats2half2_rn(C.z, C.w);
                    dst[0] = *(uint32_t*)&h0;
                    dst[1] = *(uint32_t*)&h1;
                    dst[2] = *(uint32_t*)&h2;
                    dst[3] = *(uint32_t*)&h3;
                    dst[4] = *(uint32_t*)&h4;
                    dst[5] = *(uint32_t*)&h5;
                }
            }
            int i = r * SW + 4 * c;
            *(float4*)&sm[i] = make_float4(m0, m1, m2, m3);
            __half2 qa = __floats2half2_rn(q0, q1);
            __half2 qb = __floats2half2_rn(q2, q3);
            *(uint2*)&sq[i] = make_uint2(*(uint32_t*)&qa, *(uint32_t*)&qb);
            c += 4; r += 14;                  // 256 = 14*18 + 4
            if (c >= 18) { c -= 18; r += 1; }
        }
    }
    __syncthreads();

    const int tx = threadIdx.x, tz = threadIdx.y;
    u64 acc[4];
    blur4(sm, tx, tz, acc);

#pragma unroll
    for (int oy = 0; oy < 4; oy++) {
        float lm0 = __uint_as_float((uint32_t)acc[oy]);
        float lm1 = __uint_as_float((uint32_t)(acc[oy] >> 32));
        int rm = 4 * tz + oy;                    // interior row 0..31
        int si = (rm + 4) * SW + 2 * tx + 4;
        float2 mm = *(const float2*)&sm[si];
        float2 qq = __half22float2(*(const __half2*)&sq[si]);
        float s20 = fmaxf(fmaf(lm0, fmaf(-2.f, mm.x, lm0), qq.x), 0.f);
        float s21 = fmaxf(fmaf(lm1, fmaf(-2.f, mm.y, lm1), qq.y), 0.f);

        // v = x - lm for the 2 px (6 halves from xt)
        const uint32_t* xr = (const uint32_t*)xt + rm * 96 + 3 * tx;
        float2 f0 = __half22float2(*(const __half2*)&xr[0]);  // px0c0, px0c1
        float2 f1 = __half22float2(*(const __half2*)&xr[1]);  // px0c2, px1c0
        float2 f2 = __half22float2(*(const __half2*)&xr[2]);  // px1c1, px1c2
        __half2 v0 = __floats2half2_rn(f0.x - lm0, f0.y - lm0);
        __half2 v1 = __floats2half2_rn(f1.x - lm0, f1.y - lm1);
        __half2 v2 = __floats2half2_rn(f2.x - lm1, f2.y - lm1);

        int pix = (b * HH + y0 + rm) * WW + x0 + 2 * tx;
        uint32_t* vp = (uint32_t*)g_v + pix * 3 / 2;
        __stcs(vp + 0, *(uint32_t*)&v0);
        __stcs(vp + 1, *(uint32_t*)&v1);
        __stcs(vp + 2, *(uint32_t*)&v2);
        __stcs((__half2*)&g_s2[pix], __floats2half2_rn(s20, s21));
    }
}

// ---------------------------------------------------------------------------
// Stage 2: fill ss (f32) from fp16 s2, blur -> sigma = sqrt(.), write sigma
// fp16 + per-block partials. smem = 11.5 KB static.
// ---------------------------------------------------------------------------
__global__ __launch_bounds__(256, 4) void k_stage2() {
    __shared__ __align__(16) float ss[SH2 * SW];
    __shared__ float warpsum[8];

    const int b = blockIdx.z;
    const int x0 = blockIdx.x * TX, y0 = blockIdx.y * TY;
    const int tid = threadIdx.y * 32 + threadIdx.x;

    {
        int r = tid / 18, c = tid - r * 18;
        for (int g = tid; g < SH2 * (SW / 4); g += 256) {
            int gy = y0 - 4 + r, gx = x0 - 4 + 4 * c;
            float f0 = 0, f1 = 0, f2 = 0, f3 = 0;
            if ((unsigned)gy < (unsigned)HH && (unsigned)gx < (unsigned)WW) {
                uint2 u = __ldcs((const uint2*)&g_s2[(b * HH + gy) * WW + gx]);
                float2 a = __half22float2(*(__half2*)&u.x);
                float2 d = __half22float2(*(__half2*)&u.y);
                f0 = a.x; f1 = a.y; f2 = d.x; f3 = d.y;
            }
            int i = r * SW + 4 * c;
            *(float4*)&ss[i] = make_float4(f0, f1, f2, f3);
            c += 4; r += 14;
            if (c >= 18) { c -= 18; r += 1; }
        }
    }
    __syncthreads();

    const int tx = threadIdx.x, tz = threadIdx.y;
    u64 acc[4];
    blur4(ss, tx, tz, acc);

    float lsum = 0.f;
#pragma unroll
    for (int oy = 0; oy < 4; oy++) {
        float s0 = sqrtf(fmaxf(__uint_as_float((uint32_t)acc[oy]), 0.f));
        float s1 = sqrtf(fmaxf(__uint_as_float((uint32_t)(acc[oy] >> 32)), 0.f));
        int idx = (b * HH + y0 + 4 * tz + oy) * WW + x0 + 2 * tx;
        __stcs((__half2*)&g_sig[idx], __floats2half2_rn(s0, s1));
        lsum += s0 + s1;
    }

#pragma unroll
    for (int o = 16; o > 0; o >>= 1)
        lsum += __shfl_down_sync(0xFFFFFFFFu, lsum, o);
    if (tx == 0) warpsum[tz] = lsum;
    __syncthreads();
    if (tid == 0) {
        float t = 0.f;
#pragma unroll
        for (int i = 0; i < 8; i++) t += warpsum[i];
        g_part[b * 128 + blockIdx.y * 8 + blockIdx.x] = t;
    }
}

// ---------------------------------------------------------------------------
// Final: prologue re-reduces this batch's 128 partials (L2 hits) -> ms, then
// out = v / max(ms, sigma). Reads only v + sig (fp16): 168 MB total traffic
// vs 235 MB when re-reading x. 8 px / thread.
// ---------------------------------------------------------------------------
__global__ __launch_bounds__(256) void k_final(float* __restrict__ out) {
    __shared__ float s_w[4];
    __shared__ float s_ms;

    const int b = blockIdx.x >> 7;  // 128 blocks / batch
    if (threadIdx.x < 128) {
        float v = g_part[b * 128 + threadIdx.x];
#pragma unroll
        for (int o = 16; o > 0; o >>= 1)
            v += __shfl_down_sync(0xFFFFFFFFu, v, o);
        if ((threadIdx.x & 31) == 0) s_w[threadIdx.x >> 5] = v;
    }
    __syncthreads();
    if (threadIdx.x == 0)
        s_ms = (s_w[0] + s_w[1] + s_w[2] + s_w[3]) *
               (1.f / ((float)HH * (float)WW));
    __syncthreads();
    const float ms = s_ms;

    const int p = (blockIdx.x & 127) * 2048 + threadIdx.x * 8 + (b << 18);

    // v: 8 px x 3 ch = 24 halves = 48 B = 3 x uint4 (16B-aligned: p % 8 == 0)
    const uint4* vp = (const uint4*)((const __half*)g_v + (size_t)p * 3);
    uint4 vv[3];
#pragma unroll
    for (int i = 0; i < 3; i++) vv[i] = __ldcs(vp + i);

    uint4 sgu = __ldcs((const uint4*)((const __half*)g_sig + p));
    const __half2* sgh = (const __half2*)&sgu;

    float inv[8];
#pragma unroll
    for (int i = 0; i < 4; i++) {
        float2 s = __half22float2(sgh[i]);
        inv[2 * i] = __frcp_rn(fmaxf(ms, s.x));
        inv[2 * i + 1] = __frcp_rn(fmaxf(ms, s.y));
    }

    const __half2* vh = (const __half2*)vv;  // 12 half2 = 24 values
    float4* op = (float4*)(out + (size_t)p * 3);
#pragma unroll
    for (int i = 0; i < 6; i++) {
        float2 a = __half22float2(vh[2 * i]);
        float2 d = __half22float2(vh[2 * i + 1]);
        float o0 = a.x * inv[(4 * i + 0) / 3];
        float o1 = a.y * inv[(4 * i + 1) / 3];
        float o2 = d.x * inv[(4 * i + 2) / 3];
        float o3 = d.y * inv[(4 * i + 3) / 3];
        __stcs(op + i, make_float4(o0, o1, o2, o3));
    }
}

// ---------------------------------------------------------------------------
extern "C" void kernel_launch(void* const* d_in, const int* in_sizes, int n_in,
                              void* d_out, int out_size) {
    const float* x = (const float*)d_in[0];

    cudaMemcpyToSymbolAsync(c_w, d_in[1], 81 * sizeof(float), 0,
                            cudaMemcpyDeviceToDevice, 0);

    const int smem1 = SH2 * SW * (int)sizeof(float) +
                      SH2 * SW * (int)sizeof(__half) +
                      32 * 64 * 3 * (int)sizeof(__half);  // 29568 B
    cudaFuncSetAttribute(k_stage1, cudaFuncAttributeMaxDynamicSharedMemorySize,
                         smem1);

    dim3 blk(32, 8);
    dim3 grd(WW / TX, HH / TY, BATCH);  // (8, 16, 32) = 4096 blocks
    k_stage1<<<grd, blk, smem1>>>(x);
    k_stage2<<<grd, blk>>>();
    k_final<<<BATCH * 128, 256>>>((float*)d_out);
}